// round 14
// baseline (speedup 1.0000x reference)
#include <cuda_runtime.h>
#include <cstdint>

#define NBLK 152
#define TPB  512
#define B_N  4096
#define D_N  3072
#define C_N  10
#define MAXR 27
#define NW   (TPB / 32)
#define RPT  2
#define STG  4
#define TILE_FLOATS (RPT * D_N)
#define TILE_BYTES  (TILE_FLOATS * 4)
#define SP3_PAD     34                            /* float2 slots per warp-row */
#define SP3_BYTES   (MAXR * NW * SP3_PAD * 8)
#define TILES_BYTES (STG * TILE_BYTES)
#define DYN_SMEM    (TILES_BYTES + SP3_BYTES)
#define R0BLK 23
#define REMROWS (B_N - R0BLK)
#define NB1 (NBLK - 1)

typedef unsigned long long ull;

__device__ float g_M[C_N * C_N];
__device__ float g_partial[NBLK];
__device__ unsigned int g_ticket;
__device__ unsigned int g_mflag;

__device__ __forceinline__ uint32_t smem_u32(const void* p) {
    uint32_t a;
    asm("{ .reg .u64 t; cvta.to.shared.u64 t, %1; cvt.u32.u64 %0, t; }" : "=r"(a) : "l"(p));
    return a;
}
__device__ __forceinline__ void mbar_init(uint32_t addr, uint32_t cnt) {
    asm volatile("mbarrier.init.shared.b64 [%0], %1;" :: "r"(addr), "r"(cnt) : "memory");
}
__device__ __forceinline__ void mbar_expect_tx(uint32_t addr, uint32_t bytes) {
    asm volatile("mbarrier.arrive.expect_tx.shared.b64 _, [%0], %1;" :: "r"(addr), "r"(bytes) : "memory");
}
__device__ __forceinline__ void mbar_arrive(uint32_t addr) {
    asm volatile("mbarrier.arrive.shared.b64 _, [%0];" :: "r"(addr) : "memory");
}
__device__ __forceinline__ void bulk_g2s(uint32_t dst, const void* src, uint32_t bytes, uint32_t mbar) {
    asm volatile("cp.async.bulk.shared::cta.global.mbarrier::complete_tx::bytes [%0], [%1], %2, [%3];"
                 :: "r"(dst), "l"(src), "r"(bytes), "r"(mbar) : "memory");
}
__device__ __forceinline__ void mbar_wait(uint32_t addr, uint32_t parity) {
    uint32_t done;
    asm volatile(
        "{\n\t.reg .pred p;\n\t"
        "mbarrier.try_wait.parity.shared.b64 p, [%1], %2;\n\t"
        "selp.b32 %0, 1, 0, p;\n\t}"
        : "=r"(done) : "r"(addr), "r"(parity) : "memory");
    if (!done) {
        asm volatile(
            "{\n\t.reg .pred P1;\n\t"
            "WL_%=:\n\t"
            "mbarrier.try_wait.parity.shared.b64 P1, [%0], %1, 0x989680;\n\t"
            "@P1 bra.uni WD_%=;\n\t"
            "bra.uni WL_%=;\n\t"
            "WD_%=:\n\t}"
            :: "r"(addr), "r"(parity) : "memory");
    }
}

// 3-round value-splitting reduce of z[10]; leaves (w0,w1) per lane
// (each = class partial summed over lane's 8-lane orbit; remaining sum over 4 lanes).
// Class map: c -> lanes LB[c]..LB[c]+3, slot SL[c]:
//   LB={0,0,4,8,12,16,16,20,24,28}, SL={0,1,0,0,0,0,1,0,0,0}
__device__ __forceinline__ void reduce3(const float (&z)[C_N], bool hi16, bool hi8, bool hi4,
                                        float& w0, float& w1) {
    float v[5];
#pragma unroll
    for (int j = 0; j < 5; j++) {
        float send = hi16 ? z[j] : z[j + 5];
        float oth = __shfl_xor_sync(0xffffffffu, send, 16);
        v[j] = (hi16 ? z[j + 5] : z[j]) + oth;
    }
    float u[3];
#pragma unroll
    for (int j = 0; j < 3; j++) {
        float mine = (j < 2) ? v[j + 3] : 0.f;
        float send = hi8 ? v[j] : mine;
        float oth = __shfl_xor_sync(0xffffffffu, send, 8);
        u[j] = (hi8 ? mine : v[j]) + oth;
    }
    {
        float keep0 = hi4 ? (hi8 ? u[1] : u[2]) : u[0];
        float send0 = hi4 ? u[0] : (hi8 ? u[1] : u[2]);
        float oth0 = __shfl_xor_sync(0xffffffffu, send0, 4);
        w0 = keep0 + oth0;
        float keep1 = (hi4 || hi8) ? 0.f : u[1];
        float send1 = hi4 ? u[1] : 0.f;
        float oth1 = __shfl_xor_sync(0xffffffffu, send1, 4);
        w1 = keep1 + oth1;
    }
}

// Two rows interleaved: independent FMA + interleaved 3-round reduce; full-lane STS.64.
__device__ __forceinline__ void do_rows2(const float2* __restrict__ rowA,
                                         const float2* __restrict__ rowB,
                                         int tid, int warp, int lane,
                                         const ull (&wp)[3][2][5],
                                         float2* __restrict__ sp3, int rA, int rB) {
    float2 xa0 = rowA[tid], xa1 = rowA[tid + TPB], xa2 = rowA[tid + 2 * TPB];
    float2 xb0 = rowB[tid], xb1 = rowB[tid + TPB], xb2 = rowB[tid + 2 * TPB];

    ull accA[5], accB[5];
#pragma unroll
    for (int m = 0; m < 5; m++) { accA[m] = 0ull; accB[m] = 0ull; }
#pragma unroll
    for (int j = 0; j < 3; j++)
#pragma unroll
        for (int c2 = 0; c2 < 2; c2++) {
            float xva = (j == 0) ? (c2 == 0 ? xa0.x : xa0.y)
                      : (j == 1) ? (c2 == 0 ? xa1.x : xa1.y)
                                 : (c2 == 0 ? xa2.x : xa2.y);
            float xvb = (j == 0) ? (c2 == 0 ? xb0.x : xb0.y)
                      : (j == 1) ? (c2 == 0 ? xb1.x : xb1.y)
                                 : (c2 == 0 ? xb2.x : xb2.y);
            ull xba, xbb;
            asm("mov.b64 %0, {%1, %1};" : "=l"(xba) : "f"(xva));
            asm("mov.b64 %0, {%1, %1};" : "=l"(xbb) : "f"(xvb));
#pragma unroll
            for (int m = 0; m < 5; m++) {
                asm("fma.rn.f32x2 %0, %1, %2, %0;"
                    : "+l"(accA[m]) : "l"(xba), "l"(wp[j][c2][m]));
                asm("fma.rn.f32x2 %0, %1, %2, %0;"
                    : "+l"(accB[m]) : "l"(xbb), "l"(wp[j][c2][m]));
            }
        }

    float zA[C_N], zB[C_N];
#pragma unroll
    for (int m = 0; m < 5; m++) {
        asm("mov.b64 {%0, %1}, %2;" : "=f"(zA[2*m]), "=f"(zA[2*m+1]) : "l"(accA[m]));
        asm("mov.b64 {%0, %1}, %2;" : "=f"(zB[2*m]), "=f"(zB[2*m+1]) : "l"(accB[m]));
    }

    const bool hi16 = (lane & 16) != 0;
    const bool hi8  = (lane & 8) != 0;
    const bool hi4  = (lane & 4) != 0;
    float a0, a1, b0, b1;
    reduce3(zA, hi16, hi8, hi4, a0, a1);
    reduce3(zB, hi16, hi8, hi4, b0, b1);

    sp3[(rA * NW + warp) * SP3_PAD + lane] = make_float2(a0, a1);
    sp3[(rB * NW + warp) * SP3_PAD + lane] = make_float2(b0, b1);
}

__device__ __forceinline__ void do_row(const float2* __restrict__ row,
                                       int tid, int warp, int lane,
                                       const ull (&wp)[3][2][5],
                                       float2* __restrict__ sp3, int r) {
    float2 x0 = row[tid], x1 = row[tid + TPB], x2 = row[tid + 2 * TPB];
    ull acc[5];
#pragma unroll
    for (int m = 0; m < 5; m++) acc[m] = 0ull;
#pragma unroll
    for (int j = 0; j < 3; j++)
#pragma unroll
        for (int c2 = 0; c2 < 2; c2++) {
            float xv = (j == 0) ? (c2 == 0 ? x0.x : x0.y)
                     : (j == 1) ? (c2 == 0 ? x1.x : x1.y)
                                : (c2 == 0 ? x2.x : x2.y);
            ull xb;
            asm("mov.b64 %0, {%1, %1};" : "=l"(xb) : "f"(xv));
#pragma unroll
            for (int m = 0; m < 5; m++)
                asm("fma.rn.f32x2 %0, %1, %2, %0;"
                    : "+l"(acc[m]) : "l"(xb), "l"(wp[j][c2][m]));
        }
    float z[C_N];
#pragma unroll
    for (int m = 0; m < 5; m++)
        asm("mov.b64 {%0, %1}, %2;" : "=f"(z[2*m]), "=f"(z[2*m+1]) : "l"(acc[m]));

    const bool hi16 = (lane & 16) != 0;
    const bool hi8  = (lane & 8) != 0;
    const bool hi4  = (lane & 4) != 0;
    float w0, w1;
    reduce3(z, hi16, hi8, hi4, w0, w1);
    sp3[(r * NW + warp) * SP3_PAD + lane] = make_float2(w0, w1);
}

__global__ void __launch_bounds__(TPB, 1) jacreg_kernel(
        const float* __restrict__ X, const float* __restrict__ W,
        float* __restrict__ out) {
    extern __shared__ float dynsmem[];
    float* tiles = dynsmem;                                  // STG*RPT*D_N floats
    float2* sp3 = (float2*)(dynsmem + STG * TILE_FLOATS);    // [MAXR][NW][SP3_PAD]
    __shared__ float sM[C_N * C_N];
    __shared__ float zbuf[MAXR][C_N];
    __shared__ float redM[NW][56];
    __shared__ ull mb_full[STG];
    __shared__ ull mb_cons[STG];
    __shared__ int slast;

    const int tid = threadIdx.x, b = blockIdx.x;
    const int warp = tid >> 5, lane = tid & 31;
    int r0, r1;
    if (b == 0) { r0 = 0; r1 = R0BLK; }
    else {
        r0 = R0BLK + (int)(((long long)(b - 1) * REMROWS) / NB1);
        r1 = R0BLK + (int)(((long long)b * REMROWS) / NB1);
    }
    const int nrows = r1 - r0;
    const int ntiles = (nrows + RPT - 1) / RPT;

    // W packed into f32x2 class-pairs: thread owns 6 D-positions e = (j*TPB+tid)*2+c2
    ull wp[3][2][5];
#pragma unroll
    for (int j = 0; j < 3; j++)
#pragma unroll
        for (int c2 = 0; c2 < 2; c2++) {
            int e = (j * TPB + tid) * 2 + c2;
            const ull* wrow = (const ull*)(W + (size_t)e * C_N);
#pragma unroll
            for (int m = 0; m < 5; m++) wp[j][c2][m] = wrow[m];
        }

    uint32_t full_a = smem_u32(&mb_full[0]);
    uint32_t cons_a = smem_u32(&mb_cons[0]);
    uint32_t tile_a = smem_u32(&tiles[0]);

    if (tid == 0) {
#pragma unroll
        for (int s = 0; s < STG; s++) {
            mbar_init(full_a + 8 * s, 1);
            mbar_init(cons_a + 8 * s, NW);
        }
        asm volatile("fence.proxy.async.shared::cta;" ::: "memory");
    }
    __syncthreads();

    // Prologue: fill all stages
    if (tid == 0) {
        int np = (ntiles < STG) ? ntiles : STG;
        for (int t = 0; t < np; t++) {
            int rbase = t * RPT;
            int cnt = nrows - rbase; if (cnt > RPT) cnt = RPT;
            uint32_t bytes = (uint32_t)cnt * D_N * 4;
            mbar_expect_tx(full_a + 8 * t, bytes);
            bulk_g2s(tile_a + t * TILE_BYTES,
                     X + (size_t)(r0 + rbase) * D_N, bytes, full_a + 8 * t);
        }
    }

    // Block 0: M = W^T W from wp registers; publish with release flag
    if (b == 0) {
        float w[6][C_N];
#pragma unroll
        for (int j = 0; j < 3; j++)
#pragma unroll
            for (int c2 = 0; c2 < 2; c2++)
#pragma unroll
                for (int m = 0; m < 5; m++)
                    asm("mov.b64 {%0, %1}, %2;"
                        : "=f"(w[j * 2 + c2][2 * m]), "=f"(w[j * 2 + c2][2 * m + 1])
                        : "l"(wp[j][c2][m]));
        int idx = 0;
#pragma unroll
        for (int k = 0; k < C_N; k++) {
            float a[C_N];
#pragma unroll
            for (int l = k; l < C_N; l++) {
                float s = 0.f;
#pragma unroll
                for (int pos = 0; pos < 6; pos++) s += w[pos][k] * w[pos][l];
                a[l - k] = s;
            }
#pragma unroll
            for (int off = 16; off; off >>= 1)
#pragma unroll
                for (int t = 0; t < C_N - k; t++)
                    a[t] += __shfl_xor_sync(0xffffffffu, a[t], off);
            if (lane == 0)
#pragma unroll
                for (int t = 0; t < C_N - k; t++) redM[warp][idx + t] = a[t];
            idx += C_N - k;
        }
        __syncthreads();
        if (tid < 55) {
            float s = 0.f;
#pragma unroll
            for (int wv = 0; wv < NW; wv++) s += redM[wv][tid];
            int k = 0, t = tid;
            while (t >= C_N - k) { t -= C_N - k; k++; }
            int l = k + t;
            g_M[k * C_N + l] = s;
            g_M[l * C_N + k] = s;
        }
        __syncthreads();
        if (tid == 0) {
            __threadfence();
            *(volatile unsigned int*)&g_mflag = 1u;
        }
    }

    // -------- Phase A: producer-consumer pipeline, paired rows --------
    for (int t = 0; t < ntiles; t++) {
        int s = t & (STG - 1);
        uint32_t par = (t / STG) & 1;
        mbar_wait(full_a + 8 * s, par);

        int rbase = t * RPT;
        int cnt = nrows - rbase; if (cnt > RPT) cnt = RPT;
        const float2* tile = (const float2*)(tiles + s * TILE_FLOATS);

        if (cnt == 2)
            do_rows2(tile, tile + (D_N / 2), tid, warp, lane, wp, sp3, rbase, rbase + 1);
        else
            do_row(tile, tid, warp, lane, wp, sp3, rbase);

        if (lane == 0) mbar_arrive(cons_a + 8 * s);

        if (warp == 0) {
            int tt = t + STG;
            if (tt < ntiles) {
                mbar_wait(cons_a + 8 * s, par);
                if (lane == 0) {
                    int rb = tt * RPT;
                    int c = nrows - rb; if (c > RPT) c = RPT;
                    uint32_t bytes = (uint32_t)c * D_N * 4;
                    mbar_expect_tx(full_a + 8 * s, bytes);
                    bulk_g2s(tile_a + s * TILE_BYTES,
                             X + (size_t)(r0 + rb) * D_N, bytes, full_a + 8 * s);
                }
            }
        }
    }

    // Acquire M (block0 published long ago)
    if (tid == 0) {
        volatile unsigned int* vf = &g_mflag;
        while (*vf == 0u) {}
        __threadfence();
    }
    __syncthreads();
    if (tid < C_N * C_N) sM[tid] = g_M[tid];

    // -------- Phase B1: parallel z assembly (thread per row,class) --------
    if (tid < nrows * C_N) {
        const int LB[10] = {0, 0, 4, 8, 12, 16, 16, 20, 24, 28};
        const int SL[10] = {0, 1, 0, 0, 0, 0, 1, 0, 0, 0};
        int r = tid / C_N, c = tid % C_N;
        int L = LB[c], sl = SL[c];
        float s = 0.f;
#pragma unroll
        for (int w = 0; w < NW; w++) {
            const float2* base = sp3 + (r * NW + w) * SP3_PAD + L;
#pragma unroll
            for (int l = 0; l < 4; l++) {
                float2 pv = base[l];
                s += sl ? pv.y : pv.x;
            }
        }
        zbuf[r][c] = s;
    }
    __syncthreads();

    // -------- Phase B2: one thread per row, scalar math --------
    float myreg = 0.f;
    if (tid < nrows) {
        float z[C_N];
#pragma unroll
        for (int k = 0; k < C_N; k++) z[k] = zbuf[tid][k];
        float zmax = z[0];
#pragma unroll
        for (int k = 1; k < C_N; k++) zmax = fmaxf(zmax, z[k]);
        float q[C_N], qs = 0.f;
#pragma unroll
        for (int k = 0; k < C_N; k++) { q[k] = __expf(z[k] - zmax); qs += q[k]; }
        float inv = 1.f / qs;
#pragma unroll
        for (int k = 0; k < C_N; k++) q[k] *= inv;

        const float A = 1.0f - (float)C_N * 1e-6f;
        float p[C_N], sq[C_N];
#pragma unroll
        for (int k = 0; k < C_N; k++) { p[k] = q[k] * A + 1e-6f; sq[k] = sqrtf(p[k]); }
        float sm = sq[C_N - 1], qm = q[C_N - 1];
        float om = 1.f - sm;

        float uu[C_N], Qf = 0.f;
#pragma unroll
        for (int k = 0; k < C_N; k++) {
            float t = 0.f;
#pragma unroll
            for (int l = 0; l < C_N; l++) t += sM[k * C_N + l] * q[l];
            uu[k] = t;
            Qf += q[k] * t;
        }

        float jac2 = 0.f;
        float bfac = A * qm / (sm * om * om);
#pragma unroll
        for (int i = 0; i < C_N - 1; i++) {
            float al = A * q[i] / (sq[i] * om);
            float be = sq[i] * bfac;
            float ga = al + be;
            jac2 += al * al * sM[i * C_N + i]
                  + be * be * sM[C_N * C_N - 1]
                  + ga * ga * Qf
                  + 2.f * al * be * sM[i * C_N + (C_N - 1)]
                  - 2.f * al * ga * uu[i]
                  - 2.f * be * ga * uu[C_N - 1];
        }
        float jn = sqrtf(jac2);

        float ssum = 0.f;
#pragma unroll
        for (int k = 0; k < C_N; k++) ssum += sq[k];
        float arg = ssum * 0.316227766016838f;
        arg = fminf(fmaxf(arg, -1.f), 1.f);
        float delta = 2.f * acosf(arg);

        float psum = 0.f;
#pragma unroll
        for (int k = 0; k < C_N - 1; k++) psum += p[k];
        float rho = (2.f * om - psum) / om;

        float xv = jn - delta / (rho * 0.1f);
        myreg = (xv > 0.f) ? xv : expm1f(xv);
    }

    if (warp == 0) {
#pragma unroll
        for (int off = 16; off; off >>= 1)
            myreg += __shfl_xor_sync(0xffffffffu, myreg, off);
        if (lane == 0) {
            g_partial[b] = myreg;
            __threadfence();
            unsigned int rank = atomicAdd(&g_ticket, 1u);
            slast = (rank == NBLK - 1) ? 1 : 0;
            if (rank == NBLK - 1) {
                g_ticket = 0u;
                g_mflag = 0u;
            }
        }
    }
    __syncthreads();

    if (slast && warp == 0) {
        float s = 0.f;
        for (int i = lane; i < NBLK; i += 32) s += __ldcg(&g_partial[i]);
#pragma unroll
        for (int off = 16; off; off >>= 1)
            s += __shfl_xor_sync(0xffffffffu, s, off);
        if (lane == 0) out[0] = s * (1.f / (float)B_N);
    }
}

extern "C" void kernel_launch(void* const* d_in, const int* in_sizes, int n_in,
                              void* d_out, int out_size) {
    const float* X = (const float*)d_in[0];
    const float* W = (const float*)d_in[1];
    float* out = (float*)d_out;
    cudaFuncSetAttribute(jacreg_kernel,
                         cudaFuncAttributeMaxDynamicSharedMemorySize, DYN_SMEM);
    jacreg_kernel<<<NBLK, TPB, DYN_SMEM>>>(X, W, out);
}

// round 16
// speedup vs baseline: 1.0055x; 1.0055x over previous
#include <cuda_runtime.h>
#include <cstdint>

#define NBLK 152
#define TPB  512
#define B_N  4096
#define D_N  3072
#define C_N  10
#define MAXR 27
#define NW   (TPB / 32)
#define RPT  4
#define STG  2
#define TILE_FLOATS (RPT * D_N)
#define TILE_BYTES  (TILE_FLOATS * 4)
#define SP3_PAD     34
#define SP3_BYTES   (MAXR * NW * SP3_PAD * 8)
#define TILES_BYTES (STG * TILE_BYTES)
#define DYN_SMEM    (TILES_BYTES + SP3_BYTES)
#define R0BLK 23
#define REMROWS (B_N - R0BLK)
#define NB1 (NBLK - 1)

typedef unsigned long long ull;

__device__ float g_M[C_N * C_N];
__device__ float g_partial[NBLK];
__device__ unsigned int g_ticket;
__device__ unsigned int g_mflag;

__device__ __forceinline__ uint32_t smem_u32(const void* p) {
    uint32_t a;
    asm("{ .reg .u64 t; cvta.to.shared.u64 t, %1; cvt.u32.u64 %0, t; }" : "=r"(a) : "l"(p));
    return a;
}
__device__ __forceinline__ void mbar_init(uint32_t addr, uint32_t cnt) {
    asm volatile("mbarrier.init.shared.b64 [%0], %1;" :: "r"(addr), "r"(cnt) : "memory");
}
__device__ __forceinline__ void mbar_expect_tx(uint32_t addr, uint32_t bytes) {
    asm volatile("mbarrier.arrive.expect_tx.shared.b64 _, [%0], %1;" :: "r"(addr), "r"(bytes) : "memory");
}
__device__ __forceinline__ void mbar_arrive(uint32_t addr) {
    asm volatile("mbarrier.arrive.shared.b64 _, [%0];" :: "r"(addr) : "memory");
}
__device__ __forceinline__ void bulk_g2s(uint32_t dst, const void* src, uint32_t bytes, uint32_t mbar) {
    asm volatile("cp.async.bulk.shared::cta.global.mbarrier::complete_tx::bytes [%0], [%1], %2, [%3];"
                 :: "r"(dst), "l"(src), "r"(bytes), "r"(mbar) : "memory");
}
__device__ __forceinline__ void mbar_wait(uint32_t addr, uint32_t parity) {
    uint32_t done;
    asm volatile(
        "{\n\t.reg .pred p;\n\t"
        "mbarrier.try_wait.parity.shared.b64 p, [%1], %2;\n\t"
        "selp.b32 %0, 1, 0, p;\n\t}"
        : "=r"(done) : "r"(addr), "r"(parity) : "memory");
    if (!done) {
        asm volatile(
            "{\n\t.reg .pred P1;\n\t"
            "WL_%=:\n\t"
            "mbarrier.try_wait.parity.shared.b64 P1, [%0], %1, 0x989680;\n\t"
            "@P1 bra.uni WD_%=;\n\t"
            "bra.uni WL_%=;\n\t"
            "WD_%=:\n\t}"
            :: "r"(addr), "r"(parity) : "memory");
    }
}

// 3-round value-splitting reduce of z[10]; leaves (w0,w1) per lane
// (partials over the lane's 8-lane orbit; remaining sum over 4 lanes in Phase B).
// Class map: c -> lanes LB[c]..LB[c]+3, slot SL[c]:
//   LB={0,0,4,8,12,16,16,20,24,28}, SL={0,1,0,0,0,0,1,0,0,0}
__device__ __forceinline__ void reduce3(const float (&z)[C_N], bool hi16, bool hi8, bool hi4,
                                        float& w0, float& w1) {
    float v[5];
#pragma unroll
    for (int j = 0; j < 5; j++) {
        float send = hi16 ? z[j] : z[j + 5];
        float oth = __shfl_xor_sync(0xffffffffu, send, 16);
        v[j] = (hi16 ? z[j + 5] : z[j]) + oth;
    }
    float u[3];
#pragma unroll
    for (int j = 0; j < 3; j++) {
        float mine = (j < 2) ? v[j + 3] : 0.f;
        float send = hi8 ? v[j] : mine;
        float oth = __shfl_xor_sync(0xffffffffu, send, 8);
        u[j] = (hi8 ? mine : v[j]) + oth;
    }
    {
        float keep0 = hi4 ? (hi8 ? u[1] : u[2]) : u[0];
        float send0 = hi4 ? u[0] : (hi8 ? u[1] : u[2]);
        float oth0 = __shfl_xor_sync(0xffffffffu, send0, 4);
        w0 = keep0 + oth0;
        float keep1 = (hi4 || hi8) ? 0.f : u[1];
        float send1 = hi4 ? u[1] : 0.f;
        float oth1 = __shfl_xor_sync(0xffffffffu, send1, 4);
        w1 = keep1 + oth1;
    }
}

// Two rows interleaved: independent FMA + interleaved 3-round reduce; full-lane STS.64.
__device__ __forceinline__ void do_rows2(const float2* __restrict__ rowA,
                                         const float2* __restrict__ rowB,
                                         int tid, int warp, int lane,
                                         const ull (&wp)[3][2][5],
                                         float2* __restrict__ sp3, int rA, int rB) {
    float2 xa0 = rowA[tid], xa1 = rowA[tid + TPB], xa2 = rowA[tid + 2 * TPB];
    float2 xb0 = rowB[tid], xb1 = rowB[tid + TPB], xb2 = rowB[tid + 2 * TPB];

    ull accA[5], accB[5];
#pragma unroll
    for (int m = 0; m < 5; m++) { accA[m] = 0ull; accB[m] = 0ull; }
#pragma unroll
    for (int j = 0; j < 3; j++)
#pragma unroll
        for (int c2 = 0; c2 < 2; c2++) {
            float xva = (j == 0) ? (c2 == 0 ? xa0.x : xa0.y)
                      : (j == 1) ? (c2 == 0 ? xa1.x : xa1.y)
                                 : (c2 == 0 ? xa2.x : xa2.y);
            float xvb = (j == 0) ? (c2 == 0 ? xb0.x : xb0.y)
                      : (j == 1) ? (c2 == 0 ? xb1.x : xb1.y)
                                 : (c2 == 0 ? xb2.x : xb2.y);
            ull xba, xbb;
            asm("mov.b64 %0, {%1, %1};" : "=l"(xba) : "f"(xva));
            asm("mov.b64 %0, {%1, %1};" : "=l"(xbb) : "f"(xvb));
#pragma unroll
            for (int m = 0; m < 5; m++) {
                asm("fma.rn.f32x2 %0, %1, %2, %0;"
                    : "+l"(accA[m]) : "l"(xba), "l"(wp[j][c2][m]));
                asm("fma.rn.f32x2 %0, %1, %2, %0;"
                    : "+l"(accB[m]) : "l"(xbb), "l"(wp[j][c2][m]));
            }
        }

    float zA[C_N], zB[C_N];
#pragma unroll
    for (int m = 0; m < 5; m++) {
        asm("mov.b64 {%0, %1}, %2;" : "=f"(zA[2*m]), "=f"(zA[2*m+1]) : "l"(accA[m]));
        asm("mov.b64 {%0, %1}, %2;" : "=f"(zB[2*m]), "=f"(zB[2*m+1]) : "l"(accB[m]));
    }

    const bool hi16 = (lane & 16) != 0;
    const bool hi8  = (lane & 8) != 0;
    const bool hi4  = (lane & 4) != 0;
    float a0, a1, b0, b1;
    reduce3(zA, hi16, hi8, hi4, a0, a1);
    reduce3(zB, hi16, hi8, hi4, b0, b1);

    sp3[(rA * NW + warp) * SP3_PAD + lane] = make_float2(a0, a1);
    sp3[(rB * NW + warp) * SP3_PAD + lane] = make_float2(b0, b1);
}

__device__ __forceinline__ void do_row(const float2* __restrict__ row,
                                       int tid, int warp, int lane,
                                       const ull (&wp)[3][2][5],
                                       float2* __restrict__ sp3, int r) {
    float2 x0 = row[tid], x1 = row[tid + TPB], x2 = row[tid + 2 * TPB];
    ull acc[5];
#pragma unroll
    for (int m = 0; m < 5; m++) acc[m] = 0ull;
#pragma unroll
    for (int j = 0; j < 3; j++)
#pragma unroll
        for (int c2 = 0; c2 < 2; c2++) {
            float xv = (j == 0) ? (c2 == 0 ? x0.x : x0.y)
                     : (j == 1) ? (c2 == 0 ? x1.x : x1.y)
                                : (c2 == 0 ? x2.x : x2.y);
            ull xb;
            asm("mov.b64 %0, {%1, %1};" : "=l"(xb) : "f"(xv));
#pragma unroll
            for (int m = 0; m < 5; m++)
                asm("fma.rn.f32x2 %0, %1, %2, %0;"
                    : "+l"(acc[m]) : "l"(xb), "l"(wp[j][c2][m]));
        }
    float z[C_N];
#pragma unroll
    for (int m = 0; m < 5; m++)
        asm("mov.b64 {%0, %1}, %2;" : "=f"(z[2*m]), "=f"(z[2*m+1]) : "l"(acc[m]));

    const bool hi16 = (lane & 16) != 0;
    const bool hi8  = (lane & 8) != 0;
    const bool hi4  = (lane & 4) != 0;
    float w0, w1;
    reduce3(z, hi16, hi8, hi4, w0, w1);
    sp3[(r * NW + warp) * SP3_PAD + lane] = make_float2(w0, w1);
}

__global__ void __launch_bounds__(TPB, 1) jacreg_kernel(
        const float* __restrict__ X, const float* __restrict__ W,
        float* __restrict__ out) {
    extern __shared__ float dynsmem[];
    float* tiles = dynsmem;                                  // STG*RPT*D_N floats
    float2* sp3 = (float2*)(dynsmem + STG * TILE_FLOATS);    // [MAXR][NW][SP3_PAD]
    __shared__ float sM[C_N * C_N];
    __shared__ float zbuf[MAXR][C_N];
    __shared__ float redM[NW][56];
    __shared__ ull mb_full[STG];
    __shared__ ull mb_cons[STG];
    __shared__ int slast;

    const int tid = threadIdx.x, b = blockIdx.x;
    const int warp = tid >> 5, lane = tid & 31;
    int r0, r1;
    if (b == 0) { r0 = 0; r1 = R0BLK; }
    else {
        r0 = R0BLK + (int)(((long long)(b - 1) * REMROWS) / NB1);
        r1 = R0BLK + (int)(((long long)b * REMROWS) / NB1);
    }
    const int nrows = r1 - r0;
    const int ntiles = (nrows + RPT - 1) / RPT;

    // W packed into f32x2 class-pairs: thread owns 6 D-positions e = (j*TPB+tid)*2+c2
    ull wp[3][2][5];
#pragma unroll
    for (int j = 0; j < 3; j++)
#pragma unroll
        for (int c2 = 0; c2 < 2; c2++) {
            int e = (j * TPB + tid) * 2 + c2;
            const ull* wrow = (const ull*)(W + (size_t)e * C_N);
#pragma unroll
            for (int m = 0; m < 5; m++) wp[j][c2][m] = wrow[m];
        }

    uint32_t full_a = smem_u32(&mb_full[0]);
    uint32_t cons_a = smem_u32(&mb_cons[0]);
    uint32_t tile_a = smem_u32(&tiles[0]);

    if (tid == 0) {
#pragma unroll
        for (int s = 0; s < STG; s++) {
            mbar_init(full_a + 8 * s, 1);
            mbar_init(cons_a + 8 * s, NW);
        }
        asm volatile("fence.proxy.async.shared::cta;" ::: "memory");
    }
    __syncthreads();

    // Prologue: fill both stages
    if (tid == 0) {
        int np = (ntiles < STG) ? ntiles : STG;
        for (int t = 0; t < np; t++) {
            int rbase = t * RPT;
            int cnt = nrows - rbase; if (cnt > RPT) cnt = RPT;
            uint32_t bytes = (uint32_t)cnt * D_N * 4;
            mbar_expect_tx(full_a + 8 * t, bytes);
            bulk_g2s(tile_a + t * TILE_BYTES,
                     X + (size_t)(r0 + rbase) * D_N, bytes, full_a + 8 * t);
        }
    }

    // Block 0: M = W^T W from wp registers; publish with release flag
    if (b == 0) {
        float w[6][C_N];
#pragma unroll
        for (int j = 0; j < 3; j++)
#pragma unroll
            for (int c2 = 0; c2 < 2; c2++)
#pragma unroll
                for (int m = 0; m < 5; m++)
                    asm("mov.b64 {%0, %1}, %2;"
                        : "=f"(w[j * 2 + c2][2 * m]), "=f"(w[j * 2 + c2][2 * m + 1])
                        : "l"(wp[j][c2][m]));
        int idx = 0;
#pragma unroll
        for (int k = 0; k < C_N; k++) {
            float a[C_N];
#pragma unroll
            for (int l = k; l < C_N; l++) {
                float s = 0.f;
#pragma unroll
                for (int pos = 0; pos < 6; pos++) s += w[pos][k] * w[pos][l];
                a[l - k] = s;
            }
#pragma unroll
            for (int off = 16; off; off >>= 1)
#pragma unroll
                for (int t = 0; t < C_N - k; t++)
                    a[t] += __shfl_xor_sync(0xffffffffu, a[t], off);
            if (lane == 0)
#pragma unroll
                for (int t = 0; t < C_N - k; t++) redM[warp][idx + t] = a[t];
            idx += C_N - k;
        }
        __syncthreads();
        if (tid < 55) {
            float s = 0.f;
#pragma unroll
            for (int wv = 0; wv < NW; wv++) s += redM[wv][tid];
            int k = 0, t = tid;
            while (t >= C_N - k) { t -= C_N - k; k++; }
            int l = k + t;
            g_M[k * C_N + l] = s;
            g_M[l * C_N + k] = s;
        }
        __syncthreads();
        if (tid == 0) {
            __threadfence();
            *(volatile unsigned int*)&g_mflag = 1u;
        }
    }

    // -------- Phase A: producer-consumer pipeline, paired rows, RPT=4 --------
    for (int t = 0; t < ntiles; t++) {
        int s = t & 1;
        uint32_t par = (t >> 1) & 1;
        mbar_wait(full_a + 8 * s, par);

        int rbase = t * RPT;
        int cnt = nrows - rbase; if (cnt > RPT) cnt = RPT;
        const float2* tile = (const float2*)(tiles + s * TILE_FLOATS);

        int rl = 0;
        for (; rl + 1 < cnt; rl += 2)
            do_rows2(tile + rl * (D_N / 2), tile + (rl + 1) * (D_N / 2),
                     tid, warp, lane, wp, sp3, rbase + rl, rbase + rl + 1);
        if (rl < cnt)
            do_row(tile + rl * (D_N / 2), tid, warp, lane, wp, sp3, rbase + rl);

        if (lane == 0) mbar_arrive(cons_a + 8 * s);

        if (warp == 0) {
            int tt = t + STG;
            if (tt < ntiles) {
                mbar_wait(cons_a + 8 * s, par);
                if (lane == 0) {
                    int rb = tt * RPT;
                    int c = nrows - rb; if (c > RPT) c = RPT;
                    uint32_t bytes = (uint32_t)c * D_N * 4;
                    mbar_expect_tx(full_a + 8 * s, bytes);
                    bulk_g2s(tile_a + s * TILE_BYTES,
                             X + (size_t)(r0 + rb) * D_N, bytes, full_a + 8 * s);
                }
            }
        }
    }

    // Acquire M (block0 published long ago)
    if (tid == 0) {
        volatile unsigned int* vf = &g_mflag;
        while (*vf == 0u) {}
        __threadfence();
    }
    __syncthreads();
    if (tid < C_N * C_N) sM[tid] = g_M[tid];

    // -------- Phase B1: parallel z assembly (thread per row,class) --------
    if (tid < nrows * C_N) {
        const int LB[10] = {0, 0, 4, 8, 12, 16, 16, 20, 24, 28};
        const int SL[10] = {0, 1, 0, 0, 0, 0, 1, 0, 0, 0};
        int r = tid / C_N, c = tid % C_N;
        int L = LB[c], sl = SL[c];
        float s = 0.f;
#pragma unroll
        for (int w = 0; w < NW; w++) {
            const float2* base = sp3 + (r * NW + w) * SP3_PAD + L;
#pragma unroll
            for (int l = 0; l < 4; l++) {
                float2 pv = base[l];
                s += sl ? pv.y : pv.x;
            }
        }
        zbuf[r][c] = s;
    }
    __syncthreads();

    // -------- Phase B2: one thread per row, scalar math --------
    float myreg = 0.f;
    if (tid < nrows) {
        float z[C_N];
#pragma unroll
        for (int k = 0; k < C_N; k++) z[k] = zbuf[tid][k];
        float zmax = z[0];
#pragma unroll
        for (int k = 1; k < C_N; k++) zmax = fmaxf(zmax, z[k]);
        float q[C_N], qs = 0.f;
#pragma unroll
        for (int k = 0; k < C_N; k++) { q[k] = __expf(z[k] - zmax); qs += q[k]; }
        float inv = 1.f / qs;
#pragma unroll
        for (int k = 0; k < C_N; k++) q[k] *= inv;

        const float A = 1.0f - (float)C_N * 1e-6f;
        float p[C_N], sq[C_N];
#pragma unroll
        for (int k = 0; k < C_N; k++) { p[k] = q[k] * A + 1e-6f; sq[k] = sqrtf(p[k]); }
        float sm = sq[C_N - 1], qm = q[C_N - 1];
        float om = 1.f - sm;

        float uu[C_N], Qf = 0.f;
#pragma unroll
        for (int k = 0; k < C_N; k++) {
            float t = 0.f;
#pragma unroll
            for (int l = 0; l < C_N; l++) t += sM[k * C_N + l] * q[l];
            uu[k] = t;
            Qf += q[k] * t;
        }

        float jac2 = 0.f;
        float bfac = A * qm / (sm * om * om);
#pragma unroll
        for (int i = 0; i < C_N - 1; i++) {
            float al = A * q[i] / (sq[i] * om);
            float be = sq[i] * bfac;
            float ga = al + be;
            jac2 += al * al * sM[i * C_N + i]
                  + be * be * sM[C_N * C_N - 1]
                  + ga * ga * Qf
                  + 2.f * al * be * sM[i * C_N + (C_N - 1)]
                  - 2.f * al * ga * uu[i]
                  - 2.f * be * ga * uu[C_N - 1];
        }
        float jn = sqrtf(jac2);

        float ssum = 0.f;
#pragma unroll
        for (int k = 0; k < C_N; k++) ssum += sq[k];
        float arg = ssum * 0.316227766016838f;
        arg = fminf(fmaxf(arg, -1.f), 1.f);
        float delta = 2.f * acosf(arg);

        float psum = 0.f;
#pragma unroll
        for (int k = 0; k < C_N - 1; k++) psum += p[k];
        float rho = (2.f * om - psum) / om;

        float xv = jn - delta / (rho * 0.1f);
        myreg = (xv > 0.f) ? xv : expm1f(xv);
    }

    if (warp == 0) {
#pragma unroll
        for (int off = 16; off; off >>= 1)
            myreg += __shfl_xor_sync(0xffffffffu, myreg, off);
        if (lane == 0) {
            g_partial[b] = myreg;
            __threadfence();
            unsigned int rank = atomicAdd(&g_ticket, 1u);
            slast = (rank == NBLK - 1) ? 1 : 0;
            if (rank == NBLK - 1) {
                g_ticket = 0u;
                g_mflag = 0u;
            }
        }
    }
    __syncthreads();

    if (slast && warp == 0) {
        float s = 0.f;
        for (int i = lane; i < NBLK; i += 32) s += __ldcg(&g_partial[i]);
#pragma unroll
        for (int off = 16; off; off >>= 1)
            s += __shfl_xor_sync(0xffffffffu, s, off);
        if (lane == 0) out[0] = s * (1.f / (float)B_N);
    }
}

extern "C" void kernel_launch(void* const* d_in, const int* in_sizes, int n_in,
                              void* d_out, int out_size) {
    const float* X = (const float*)d_in[0];
    const float* W = (const float*)d_in[1];
    float* out = (float*)d_out;
    cudaFuncSetAttribute(jacreg_kernel,
                         cudaFuncAttributeMaxDynamicSharedMemorySize, DYN_SMEM);
    jacreg_kernel<<<NBLK, TPB, DYN_SMEM>>>(X, W, out);
}